// round 17
// baseline (speedup 1.0000x reference)
#include <cuda_runtime.h>

// Problem constants (fixed by reference): x[256, 4096, 32] -> out[256, 64, 64, 32]
#define BATCH 256
#define TLEN  4096
#define CH    32
#define PAA   64
#define BINSZ 64   // TLEN / PAA

// FINAL — measured session optimum (reproduced twice: 49.63 / 49.95 us wall).
// One block per batch element. 1024 threads = 32 warps.
// Phase 1: warp w reduces t in [128w, 128w+128): per-channel min/max + 2 bin sums
//          (bins 2w and 2w+1), all in registers. Coalesced 128B rows, lane=channel;
//          32 independent scalar LDG.32.CS per thread (streaming: input marked
//          evict-first so L2 stays available for dirty output writeback).
// Phase 2: cross-warp min/max reduction (padded smem transpose + shuffle).
// Phase 3: p = (binsum/64 - min)/(max-min), y = sqrt(1 - p^2) into smem.
// Phase 4: out[b,i,j,c] = y_i*p_j - p_i*y_j, float4, write-back STG.128 (dirty
//          output drains from L2 lazily, overlapping the next replay's reads).
__global__ __launch_bounds__(1024)
void gaf_gadf_kernel(const float* __restrict__ x, float* __restrict__ out) {
    __shared__ float sp[PAA][CH];       // bin sums, then p   (8 KB)
    __shared__ float sy[PAA][CH];       // y                  (8 KB)
    __shared__ float smmn[32][33];      // per-warp per-channel min (padded)
    __shared__ float smmx[32][33];      // per-warp per-channel max (padded)
    __shared__ float smin[CH];
    __shared__ float smax[CH];

    const int tid  = threadIdx.x;
    const int lane = tid & 31;
    const int warp = tid >> 5;          // 0..31
    const int b    = blockIdx.x;

    const float* xb = x + (size_t)b * (TLEN * CH);

    // ---------------- Phase 1: register-resident reduction ----------------
    // Warp w handles channel `lane`, t = 128*warp + k, k in [0,128).
    const float* base = xb + (size_t)(128 * warp) * CH + lane;
    float s0 = 0.0f, s1 = 0.0f;
    float vmin = 3.402823466e38f, vmax = -3.402823466e38f;
    #pragma unroll 8
    for (int k = 0; k < BINSZ; ++k) {
        float a = __ldcs(&base[k * CH]);
        s0 += a;
        vmin = fminf(vmin, a);
        vmax = fmaxf(vmax, a);
    }
    #pragma unroll 8
    for (int k = BINSZ; k < 2 * BINSZ; ++k) {
        float a = __ldcs(&base[k * CH]);
        s1 += a;
        vmin = fminf(vmin, a);
        vmax = fmaxf(vmax, a);
    }
    sp[2 * warp + 0][lane] = s0;
    sp[2 * warp + 1][lane] = s1;
    smmn[warp][lane] = vmin;
    smmx[warp][lane] = vmax;
    __syncthreads();

    // ---------------- Phase 2: cross-warp min/max (warp w -> channel w) ----
    {
        float m = smmn[lane][warp];     // padded: stride 33 -> conflict-free
        float M = smmx[lane][warp];
        #pragma unroll
        for (int o = 16; o > 0; o >>= 1) {
            m = fminf(m, __shfl_xor_sync(0xffffffffu, m, o));
            M = fmaxf(M, __shfl_xor_sync(0xffffffffu, M, o));
        }
        if (lane == 0) { smin[warp] = m; smax[warp] = M; }
    }
    __syncthreads();

    // ---------------- Phase 3: p and y ----------------
    #pragma unroll
    for (int idx = tid; idx < PAA * CH; idx += 1024) {
        int c = idx & (CH - 1);
        float mn  = smin[c];
        float inv = 1.0f / (smax[c] - mn);
        float pv  = ((&sp[0][0])[idx] * (1.0f / BINSZ) - mn) * inv;
        (&sp[0][0])[idx] = pv;
        (&sy[0][0])[idx] = sqrtf(fmaxf(0.0f, 1.0f - pv * pv));
    }
    __syncthreads();

    // ---------------- Phase 4: GADF outer products, float4 stores ----------
    // thread -> (c4 = tid&7 : 4-channel group, j = (tid>>3)&63, i0 = tid>>9)
    const int c4 = (tid & 7) * 4;
    const int j  = (tid >> 3) & 63;
    const int i0 = tid >> 9;            // 0 or 1; i strides by 2

    const float4 pj = *(const float4*)&sp[j][c4];
    const float4 yj = *(const float4*)&sy[j][c4];

    float* ob = out + (size_t)b * (PAA * PAA * CH) + (size_t)j * CH + c4;
    #pragma unroll 4
    for (int i = i0; i < PAA; i += 2) {
        const float4 pi = *(const float4*)&sp[i][c4];   // warp-uniform i: broadcast
        const float4 yi = *(const float4*)&sy[i][c4];
        float4 o;
        o.x = yi.x * pj.x - pi.x * yj.x;
        o.y = yi.y * pj.y - pi.y * yj.y;
        o.z = yi.z * pj.z - pi.z * yj.z;
        o.w = yi.w * pj.w - pi.w * yj.w;
        *(float4*)(ob + (size_t)i * (PAA * CH)) = o;    // write-back STG.128
    }
}

extern "C" void kernel_launch(void* const* d_in, const int* in_sizes, int n_in,
                              void* d_out, int out_size) {
    const float* x = (const float*)d_in[0];
    float* out = (float*)d_out;
    gaf_gadf_kernel<<<BATCH, 1024>>>(x, out);
}